// round 10
// baseline (speedup 1.0000x reference)
#include <cuda_runtime.h>
#include <cstdint>

// Problem constants
static constexpr int Lc  = 32;
static constexpr int Kc  = 4;
static constexpr int Dc  = 1024;
static constexpr int QOc = 1024;
static constexpr int KVc = 256;
static constexpr int FFc = 2816;

typedef unsigned long long ull;

// Scratch for per-slice partial sums (device globals: allowed scratch).
// scratchM[l][su(6)][j(12)][d(1024)], scratchQ/O[l][su(2)][k(4)][d(1024)]
__device__ float scratchM[32 * 6 * 12 * 1024];
__device__ float scratchQ[32 * 2 * 4 * 1024];
__device__ float scratchO[32 * 2 * 4 * 1024];

// ---------------- f32x2 packed ops (sm_103a) ----------------
__device__ __forceinline__ ull mul2(ull a, ull b) {
    ull d; asm("mul.rn.f32x2 %0, %1, %2;" : "=l"(d) : "l"(a), "l"(b)); return d;
}
__device__ __forceinline__ void fma2(ull& acc, ull a, ull b) {
    asm("fma.rn.f32x2 %0, %1, %2, %0;" : "+l"(acc) : "l"(a), "l"(b));
}
__device__ __forceinline__ float hsum2(ull v) {
    return __uint_as_float((uint32_t)v) + __uint_as_float((uint32_t)(v >> 32));
}

// =====================================================================
// Unit body: stream 128 weight rows x (CPL*128) cols; 4 cursed vecs
// stationary in registers; DEPTH-row register pipeline (distance DEPTH-1,
// prefetch slot != consume slot, so no copies).
// Lane layout per row: lane covers cols {p*128 + lane*4 .. +3} for p<CPL.
// After split-tree reduce, lane v*8+rr keeps (row rr%8, vec v); one STG
// per lane per 8 rows.
// =====================================================================
template<int CPL, int DEPTH>
__device__ __forceinline__ void run_unit(const float* __restrict__ wp,
                                         const float* __restrict__ cp,
                                         float* __restrict__ sp,
                                         int I, int lane)
{
    // Cursed vectors: 4 vecs x CPL double2 (2*CPL ull each).
    ull cc[4][2 * CPL];
#pragma unroll
    for (int v = 0; v < 4; ++v)
#pragma unroll
        for (int p = 0; p < CPL; ++p) {
            const double2 d = *reinterpret_cast<const double2*>(
                cp + (size_t)v * I + p * 128);
            cc[v][2 * p]     = __double_as_longlong(d.x);
            cc[v][2 * p + 1] = __double_as_longlong(d.y);
        }

    // Weight pipeline: DEPTH rows.
    ull wb[DEPTH][2 * CPL];
#pragma unroll
    for (int r = 0; r < DEPTH; ++r)
#pragma unroll
        for (int p = 0; p < CPL; ++p) {
            const double2 d = *reinterpret_cast<const double2*>(
                wp + (size_t)r * I + p * 128);
            wb[r][2 * p]     = __double_as_longlong(d.x);
            wb[r][2 * p + 1] = __double_as_longlong(d.y);
        }

    const int  myv  = lane >> 3;
    const bool lo16 = lane < 16;
    const bool bit3 = (lane & 8) != 0;
    float mine = 0.f;

    for (int g = 0; g < 16; ++g) {
#pragma unroll
        for (int rr = 0; rr < 8; ++rr) {
            const int r    = g * 8 + rr;
            const int slot = rr % DEPTH;

            // Prefetch row r+DEPTH-1 into slot (r+DEPTH-1)%DEPTH (!= slot;
            // its old row r-1 was consumed last iteration). Wrap for tail.
            {
                const int pr = (r + DEPTH - 1) & 127;
                const int ps = (rr + DEPTH - 1) % DEPTH;
                const float* wr = wp + (size_t)pr * I;
#pragma unroll
                for (int p = 0; p < CPL; ++p) {
                    const double2 d = *reinterpret_cast<const double2*>(wr + p * 128);
                    wb[ps][2 * p]     = __double_as_longlong(d.x);
                    wb[ps][2 * p + 1] = __double_as_longlong(d.y);
                }
            }

            // Per-vec dot partial over this lane's CPL*4 columns.
            ull t0 = mul2(wb[slot][0], cc[0][0]);
            ull t1 = mul2(wb[slot][0], cc[1][0]);
            ull t2 = mul2(wb[slot][0], cc[2][0]);
            ull t3 = mul2(wb[slot][0], cc[3][0]);
#pragma unroll
            for (int p = 1; p < 2 * CPL; ++p) {
                fma2(t0, wb[slot][p], cc[0][p]);
                fma2(t1, wb[slot][p], cc[1][p]);
                fma2(t2, wb[slot][p], cc[2][p]);
                fma2(t3, wb[slot][p], cc[3][p]);
            }
            const float f0 = hsum2(t0), f1 = hsum2(t1);
            const float f2 = hsum2(t2), f3 = hsum2(t3);

            // Split-tree 32-lane reduction of 4 values (~6 shfl).
            // After: value v's full sum lives on lanes [v*8, v*8+8).
            const float ka = lo16 ? f0 : f2, sa = lo16 ? f2 : f0;
            const float g0 = ka + __shfl_xor_sync(0xffffffffu, sa, 16);
            const float kb = lo16 ? f1 : f3, sb = lo16 ? f3 : f1;
            const float g1 = kb + __shfl_xor_sync(0xffffffffu, sb, 16);
            const float kc = bit3 ? g1 : g0, sc = bit3 ? g0 : g1;
            float h = kc + __shfl_xor_sync(0xffffffffu, sc, 8);
            h += __shfl_xor_sync(0xffffffffu, h, 4);
            h += __shfl_xor_sync(0xffffffffu, h, 2);
            h += __shfl_xor_sync(0xffffffffu, h, 1);

            if ((lane & 7) == rr) mine = h;
        }
        // One store per 8 rows: lane -> (v = lane>>3, row = lane&7).
        sp[(size_t)myv * 1024 + g * 8 + (lane & 7)] = mine;
    }
}

// =====================================================================
// Kernel A: warp-autonomous projection partials.
// Warp unit = (matrix, layer, 4-vec group, 128-row chunk, col slice).
// Slices: 512 cols (CPL=4, depth 2) or 256 cols (CPL=2, depth 4).
// Units: MLP 4608 (vg fastest => weight sharing via L1/L2)
//        Q 512 | O 512 | K 256 | V 256   -> 6144 = 768 blocks x 8 warps.
// =====================================================================
extern "C" __global__ void __launch_bounds__(256, 2)
proj_partials(const float* __restrict__ cq, const float* __restrict__ ck,
              const float* __restrict__ cv, const float* __restrict__ co,
              const float* __restrict__ cm,
              const float* __restrict__ Wq, const float* __restrict__ Wk,
              const float* __restrict__ Wv, const float* __restrict__ Wo,
              const float* __restrict__ Wd,
              float* __restrict__ out)
{
    const int lane = threadIdx.x & 31;
    const int u    = blockIdx.x * 8 + (threadIdx.x >> 5);

    if (u < 4608) {                       // MLP (W_down; 12 vecs in 3 groups)
        const int vg = u % 3;  int t = u / 3;
        const int su = t % 6;  t /= 6;
        const int rc = t & 7;  const int l = t >> 3;
        const int row0 = rc * 128;
        const float* wbase = Wd + ((size_t)l * Dc + row0) * FFc + lane * 4;
        const float* cbase = cm + ((size_t)l * 12 + vg * 4) * FFc + lane * 4;
        float* sp = scratchM + (size_t)((l * 6 + su) * 12 + vg * 4) * 1024 + row0;
        if (su < 5)
            run_unit<4, 2>(wbase + su * 512, cbase + su * 512, sp, FFc, lane);
        else
            run_unit<2, 4>(wbase + 2560, cbase + 2560, sp, FFc, lane);
    } else if (u < 5632) {                // Q or O (I=1024: 2 wide slices)
        int t = u - 4608;
        const bool isO = t >= 512; if (isO) t -= 512;
        const int su = t & 1;  t >>= 1;
        const int rc = t & 7;  const int l = t >> 3;
        const int row0 = rc * 128, c0 = su * 512;
        const float* W = isO ? Wo : Wq;
        const float* C = isO ? co : cq;
        float* sp = (isO ? scratchO : scratchQ)
                    + (size_t)((l * 2 + su) * 4) * 1024 + row0;
        run_unit<4, 2>(W + ((size_t)l * Dc + row0) * QOc + c0 + lane * 4,
                       C + (size_t)l * 4 * QOc + c0 + lane * 4, sp, QOc, lane);
    } else {                              // K or V (I=256: direct to out)
        int t = u - 5632;
        const bool isV = t >= 256; if (isV) t -= 256;
        const int rc = t & 7;  const int l = t >> 3;
        const int row0 = rc * 128;
        const float* W = isV ? Wv : Wk;
        const float* C = isV ? cv : ck;
        const int m = isV ? 2 : 1;
        float* sp = out + (size_t)(((l * 7 + m) * 2 + 1) * 4) * 1024 + row0;
        run_unit<2, 4>(W + ((size_t)l * Dc + row0) * KVc + lane * 4,
                       C + (size_t)l * 4 * KVc + lane * 4, sp, KVc, lane);
    }
}

// =====================================================================
// Kernel B: reduce partials over slices, write outputs, residual copy.
// Segments (256-thr blocks):
//   [0, 393216)       MLP reduce (6 partials)    -> 1536 blocks
//   [393216, 524288)  Q reduce (2 partials)      -> 512 blocks
//   [524288, 655360)  O reduce (2 partials)      -> 512 blocks
//   [655360, 884736)  residual copy (float4)     -> 896 blocks
// =====================================================================
extern "C" __global__ void __launch_bounds__(256)
reduce_out(const float* __restrict__ residual, float* __restrict__ out)
{
    const int x = blockIdx.x * 256 + threadIdx.x;

    if (x < 393216) {                       // MLP
        const int d = x & 1023;
        int t = x >> 10;
        const int j = t % 12, l = t / 12;
        const float* p = scratchM + (size_t)(l * 6 * 12 + j) * 1024 + d;
        float s = 0.f;
#pragma unroll
        for (int si = 0; si < 6; ++si) s += p[(size_t)si * 12 * 1024];
        const int mi = j >> 2;
        const int m  = (mi == 2) ? 6 : (3 + mi);
        const int k  = j & 3;
        out[(size_t)(((l * 7 + m) * 2 + 1) * 4 + k) * 1024 + d] = s;
    } else if (x < 524288) {                // Q (m=0)
        const int y = x - 393216;
        const int d = y & 1023;
        int t = y >> 10;
        const int k = t & 3, l = t >> 2;
        const float* p = scratchQ + (size_t)(l * 8 + k) * 1024 + d;
        const float s = p[0] + p[(size_t)4 * 1024];
        out[(size_t)(((l * 7 + 0) * 2 + 1) * 4 + k) * 1024 + d] = s;
    } else if (x < 655360) {                // O (m=5)
        const int y = x - 524288;
        const int d = y & 1023;
        int t = y >> 10;
        const int k = t & 3, l = t >> 2;
        const float* p = scratchO + (size_t)(l * 8 + k) * 1024 + d;
        const float s = p[0] + p[(size_t)4 * 1024];
        out[(size_t)(((l * 7 + 5) * 2 + 1) * 4 + k) * 1024 + d] = s;
    } else {                                // residual copy (s=0 rows)
        const int i = x - 655360;           // < 229376 float4
        const float4* r4 = reinterpret_cast<const float4*>(residual);
        float4* o4 = reinterpret_cast<float4*>(out);
        const int chunk  = i >> 10;         // (l,m) chunk: 1024 float4 each
        const int within = i & 1023;
        o4[(size_t)chunk * 2048 + within] = r4[i];
    }
}

extern "C" void kernel_launch(void* const* d_in, const int* in_sizes, int n_in,
                              void* d_out, int out_size)
{
    const float* residual = (const float*)d_in[0];
    const float* cq       = (const float*)d_in[1];
    const float* ck       = (const float*)d_in[2];
    const float* cv       = (const float*)d_in[3];
    const float* co       = (const float*)d_in[4];
    const float* cm       = (const float*)d_in[5];
    const float* Wq       = (const float*)d_in[6];
    const float* Wk       = (const float*)d_in[7];
    const float* Wv       = (const float*)d_in[8];
    const float* Wo       = (const float*)d_in[9];
    const float* Wd       = (const float*)d_in[10];
    float* out            = (float*)d_out;

    proj_partials<<<768, 256>>>(cq, ck, cv, co, cm,
                                Wq, Wk, Wv, Wo, Wd, out);
    reduce_out<<<3456, 256>>>(residual, out);
}

// round 11
// speedup vs baseline: 1.5327x; 1.5327x over previous
#include <cuda_runtime.h>
#include <cstdint>

// Problem constants
static constexpr int Lc  = 32;
static constexpr int Kc  = 4;
static constexpr int Dc  = 1024;
static constexpr int QOc = 1024;
static constexpr int KVc = 256;
static constexpr int FFc = 2816;

typedef unsigned long long ull;

// Per-warp smem: 3 buffers x (512 w-floats + 192 c-floats) = 2112 floats.
static constexpr int WB_FL = 704;          // floats per buffer
static constexpr int PW_FL = 3 * WB_FL;    // 2112 floats per warp
static constexpr int SMEM_BYTES = 8 * PW_FL * 4;   // 67584 B per CTA

// ---------------- f32x2 packed FMA (sm_103a) ----------------
__device__ __forceinline__ void fma2(ull& acc, ull a, ull b) {
    asm("fma.rn.f32x2 %0, %1, %2, %0;" : "+l"(acc) : "l"(a), "l"(b));
}
__device__ __forceinline__ float hsum2(ull v) {
    return __uint_as_float((uint32_t)v) + __uint_as_float((uint32_t)(v >> 32));
}

// ---------------- cp.async helpers ----------------
__device__ __forceinline__ void cp_async16(uint32_t saddr, const void* gptr) {
    asm volatile("cp.async.cg.shared.global [%0], [%1], 16;" :: "r"(saddr), "l"(gptr));
}
__device__ __forceinline__ void cp_commit() {
    asm volatile("cp.async.commit_group;");
}
template<int N>
__device__ __forceinline__ void cp_wait() {
    asm volatile("cp.async.wait_group %0;" :: "n"(N));
}

// =====================================================================
// run_unit: warp-private streaming GEMV, lane = row.
// Unit = 32 rows x I cols, M vecs. Tiles of 16 cols staged via cp.async
// into a per-warp triple-buffered smem slab; weights read back with a
// conflict-free swizzled LDS.128 (lane reads its own row), cursed quads
// via LDS broadcast. No cross-lane reduction; acc[M] per lane (its row).
// Sync: __syncwarp only. Prefetch distance 2, issued before compute.
// =====================================================================
template<int M, int I>
__device__ __forceinline__ void run_unit(const float* __restrict__ Wg,  // +row0*I
                                         const float* __restrict__ Cg,  // vec v at +v*I
                                         float* __restrict__ swarp,
                                         ull* __restrict__ acc,
                                         int lane)
{
    constexpr int NT = I / 16;
    const uint32_t sb = (uint32_t)__cvta_generic_to_shared(swarp);

    auto stage = [&](int ct, int buf) {
        const int c0 = ct * 16;
        const uint32_t bb = sb + (uint32_t)buf * (WB_FL * 4);
        // Weights: 32 rows x 64 B = 128 16B-transfers, 4 per lane. Swizzled dst.
#pragma unroll
        for (int i = 0; i < 4; ++i) {
            const int t    = i * 32 + lane;
            const int row  = t >> 2;
            const int quad = t & 3;
            const uint32_t dst = bb + (uint32_t)(row * 64 + ((quad ^ ((row >> 1) & 3)) * 16));
            cp_async16(dst, Wg + (size_t)row * I + c0 + quad * 4);
        }
        // Cursed: M x 16 floats = M*4 transfers (<= 48).
#pragma unroll
        for (int i = 0; i < (M * 4 + 31) / 32; ++i) {
            const int t = i * 32 + lane;
            if (t < M * 4) {
                const int v = t >> 2, cq = t & 3;
                cp_async16(bb + 2048u + (uint32_t)(v * 64 + cq * 16),
                           Cg + (size_t)v * I + c0 + cq * 4);
            }
        }
    };

    stage(0, 0); cp_commit();
    stage(1, 1); cp_commit();

    const int swz = (lane >> 1) & 3;      // row-dependent quad swizzle
    int buf = 0;
    for (int ct = 0; ct < NT; ++ct) {
        cp_wait<1>();
        __syncwarp();
        // Prefetch tile ct+2 into buffer (buf+2)%3 (tile ct-1's slot; all
        // lanes finished it before the syncwarp above).
        if (ct + 2 < NT) stage(ct + 2, (buf == 0) ? 2 : buf - 1);
        cp_commit();

        const float* wb   = swarp + buf * WB_FL;
        const float* wrow = wb + lane * 16;
        const float* cb   = wb + 512;
#pragma unroll
        for (int q = 0; q < 4; ++q) {
            const double2 wd = *reinterpret_cast<const double2*>(wrow + ((q ^ swz) * 4));
            const ull w01 = __double_as_longlong(wd.x);
            const ull w23 = __double_as_longlong(wd.y);
#pragma unroll
            for (int v = 0; v < M; ++v) {
                const double2 cd = *reinterpret_cast<const double2*>(cb + v * 16 + q * 4);
                fma2(acc[v], w01, __double_as_longlong(cd.x));
                fma2(acc[v], w23, __double_as_longlong(cd.y));
            }
        }
        buf = (buf == 2) ? 0 : buf + 1;
    }
}

// =====================================================================
// Fused kernel. Proj blocks [0,640): 8 warps each, warp-unit =
// (matrix, layer l, 32-row chunk rc). Units:
//   [0,1024)    MLP (all 12 vecs/unit -> weights streamed ONCE)
//   [1024,2048) Q   [2048,3072) O   [3072,4096) K   [4096,5120) V
// Copy blocks [640,696): residual -> out (s=0 rows), 4096 float4 each.
// Output row(l,m,k) = l*56 + m*8 + 4 + k (projected side s=1).
// =====================================================================
extern "C" __global__ void __launch_bounds__(256, 2)
both_sides_fused(const float* __restrict__ residual,
                 const float* __restrict__ cq, const float* __restrict__ ck,
                 const float* __restrict__ cv, const float* __restrict__ co,
                 const float* __restrict__ cm,
                 const float* __restrict__ Wq, const float* __restrict__ Wk,
                 const float* __restrict__ Wv, const float* __restrict__ Wo,
                 const float* __restrict__ Wd,
                 float* __restrict__ out)
{
    extern __shared__ __align__(16) float smem[];

    const int b = blockIdx.x;
    if (b >= 640) {                       // residual copy
        const float4* r4 = reinterpret_cast<const float4*>(residual);
        float4* o4 = reinterpret_cast<float4*>(out);
        const int i0 = (b - 640) * 4096 + (int)threadIdx.x;
#pragma unroll
        for (int j = 0; j < 16; ++j) {
            const int i = i0 + j * 256;   // < 229376
            const int chunk  = i >> 10;   // (l,m): 1024 float4 per chunk
            const int within = i & 1023;
            o4[(size_t)chunk * 2048 + within] = r4[i];
        }
        return;
    }

    const int lane = threadIdx.x & 31;
    const int warp = threadIdx.x >> 5;
    const int u    = b * 8 + warp;
    float* swarp = smem + warp * PW_FL;

    if (u < 1024) {                                   // MLP: 12 vecs
        const int l = u >> 5, rc = u & 31;
        const int row0 = rc * 32, col = row0 + lane;
        ull acc[12];
#pragma unroll
        for (int v = 0; v < 12; ++v) acc[v] = 0ull;
        run_unit<12, FFc>(Wd + ((size_t)l * Dc + row0) * FFc,
                          cm + (size_t)l * 12 * FFc, swarp, acc, lane);
#pragma unroll
        for (int v = 0; v < 12; ++v) {
            const int mi = v >> 2;                    // 0,1,2 -> gate,up,down
            const int m  = (mi == 2) ? 6 : (3 + mi);  // gate=3, up=4, down=6
            const int k  = v & 3;
            out[(size_t)(l * 56 + m * 8 + 4 + k) * 1024 + col] = hsum2(acc[v]);
        }
    } else if (u < 3072) {                            // Q (m=0) / O (m=5)
        int t = u - 1024;
        const bool isO = t >= 1024; if (isO) t -= 1024;
        const int l = t >> 5, rc = t & 31;
        const int row0 = rc * 32, col = row0 + lane;
        const float* W = isO ? Wo : Wq;
        const float* C = isO ? co : cq;
        const int m = isO ? 5 : 0;
        ull acc[4];
#pragma unroll
        for (int v = 0; v < 4; ++v) acc[v] = 0ull;
        run_unit<4, QOc>(W + ((size_t)l * Dc + row0) * QOc,
                         C + (size_t)l * 4 * QOc, swarp, acc, lane);
#pragma unroll
        for (int v = 0; v < 4; ++v)
            out[(size_t)(l * 56 + m * 8 + 4 + v) * 1024 + col] = hsum2(acc[v]);
    } else {                                          // K (m=1) / V (m=2)
        int t = u - 3072;
        const bool isV = t >= 1024; if (isV) t -= 1024;
        const int l = t >> 5, rc = t & 31;
        const int row0 = rc * 32, col = row0 + lane;
        const float* W = isV ? Wv : Wk;
        const float* C = isV ? cv : ck;
        const int m = isV ? 2 : 1;
        ull acc[4];
#pragma unroll
        for (int v = 0; v < 4; ++v) acc[v] = 0ull;
        run_unit<4, KVc>(W + ((size_t)l * Dc + row0) * KVc,
                         C + (size_t)l * 4 * KVc, swarp, acc, lane);
#pragma unroll
        for (int v = 0; v < 4; ++v)
            out[(size_t)(l * 56 + m * 8 + 4 + v) * 1024 + col] = hsum2(acc[v]);
    }
}

extern "C" void kernel_launch(void* const* d_in, const int* in_sizes, int n_in,
                              void* d_out, int out_size)
{
    const float* residual = (const float*)d_in[0];
    const float* cq       = (const float*)d_in[1];
    const float* ck       = (const float*)d_in[2];
    const float* cv       = (const float*)d_in[3];
    const float* co       = (const float*)d_in[4];
    const float* cm       = (const float*)d_in[5];
    const float* Wq       = (const float*)d_in[6];
    const float* Wk       = (const float*)d_in[7];
    const float* Wv       = (const float*)d_in[8];
    const float* Wo       = (const float*)d_in[9];
    const float* Wd       = (const float*)d_in[10];
    float* out            = (float*)d_out;

    static bool attr_set = false;
    if (!attr_set) {
        cudaFuncSetAttribute(both_sides_fused,
                             cudaFuncAttributeMaxDynamicSharedMemorySize,
                             SMEM_BYTES);
        attr_set = true;
    }

    both_sides_fused<<<696, 256, SMEM_BYTES>>>(residual, cq, ck, cv, co, cm,
                                               Wq, Wk, Wv, Wo, Wd, out);
}